// round 5
// baseline (speedup 1.0000x reference)
#include <cuda_runtime.h>
#include <math.h>
#include <stdint.h>

#define L_ALLC 2048
#define L_TXTC 512
#define L_IMGC 1536
#define NH     24
#define DHC    128
#define DIMC   3072
#define QKVD   9216
#define MLPD   12288

// ---------------- scratch (device globals; no runtime allocation) ----------------
__device__ float g_xmod  [L_ALLC * DIMC];
__device__ float g_qkv   [L_ALLC * QKVD];
__device__ float g_q     [NH * L_ALLC * DHC];
__device__ float g_k     [NH * L_ALLC * DHC];
__device__ float g_vt    [NH * DHC * L_ALLC];
__device__ float g_S     [(size_t)NH * L_ALLC * L_ALLC];
__device__ float g_ocat  [L_ALLC * DIMC];
__device__ float g_attno [L_ALLC * DIMC];
__device__ float g_xres  [L_ALLC * DIMC];
__device__ float g_mlpin [L_ALLC * DIMC];
__device__ float g_hid   [L_ALLC * MLPD];
__device__ float g_mlpo  [L_ALLC * DIMC];

__device__ __forceinline__ float gelu_tanh(float x) {
    float x3 = x * x * x;
    return 0.5f * x * (1.0f + tanhf(0.7978845608028654f * (x + 0.044715f * x3)));
}

__device__ __forceinline__ void cp_async16(uint32_t smem_addr, const void* gptr) {
    asm volatile("cp.async.cg.shared.global [%0], [%1], 16;\n"
                 :: "r"(smem_addr), "l"(gptr));
}
__device__ __forceinline__ void cp_commit() {
    asm volatile("cp.async.commit_group;\n");
}
__device__ __forceinline__ void cp_wait1() {
    asm volatile("cp.async.wait_group 1;\n");
}

// ---------------- tf32 mma GEMM, 256x128 CTA tile, 3-stage cp.async --------------
// C = A(MxK) * B(NxK)^T + bias, opt GELU. 256 threads, 8 warps (4x2),
// warp tile 64x64, mma.m16n8k8.tf32 (raw fp32 bits; HW truncates mantissa).
// Smem row stride 36 words -> conflict-free fragment gathers.
// grid.x decoded M-fastest so concurrent CTAs share B (weight) tiles in L2.
#define A_SLAB_F (256 * 36)
#define B_SLAB_F (128 * 36)
#define STAGE_F  (A_SLAB_F + B_SLAB_F)
#define GSMEM_BYTES (3 * STAGE_F * 4)

__global__ __launch_bounds__(256, 1)
void gemm_tf32_kernel(const float* __restrict__ A, long lda, long sA,
                      const float* __restrict__ B, long ldb, long sB,
                      const float* __restrict__ bias,
                      float* __restrict__ C, long ldc, long sC,
                      int M, int K, int act)
{
    extern __shared__ float sm[];

    const int tid = threadIdx.x;
    const int nm = M >> 8;
    const int bm = blockIdx.x % nm;
    const int bn = blockIdx.x / nm;
    const int bz = blockIdx.z;

    const float* Ag = A + (long)bz * sA + (long)bm * 256 * lda;
    const float* Bg = B + (long)bz * sB + (long)bn * 128 * ldb;

    const int lane = tid & 31, warp = tid >> 5;
    const int wm = (warp >> 1) * 64;
    const int wn = (warp & 1) * 64;
    const int qr = lane >> 2, qc = lane & 3;

    float* Asf[3];
    float* Bsf[3];
    uint32_t Asa[3], Bsa[3];
#pragma unroll
    for (int s = 0; s < 3; s++) {
        Asf[s] = sm + s * STAGE_F;
        Bsf[s] = Asf[s] + A_SLAB_F;
        Asa[s] = (uint32_t)__cvta_generic_to_shared(Asf[s]);
        Bsa[s] = (uint32_t)__cvta_generic_to_shared(Bsf[s]);
    }

    // producer: one BK=32 slab (A: 256x32, B: 128x32), 8+4 float4 per thread
    #define LOAD_SLAB(s, k0)                                                     \
    do {                                                                         \
        uint32_t _ab = Asa[s], _bb = Bsa[s];                                     \
        _Pragma("unroll")                                                        \
        for (int i = 0; i < 8; i++) {                                            \
            int idx = tid + i * 256;                                             \
            int row = idx >> 3;                                                  \
            int c4  = (idx & 7) * 4;                                             \
            cp_async16(_ab + (uint32_t)(row * 36 + c4) * 4u,                     \
                       Ag + (long)row * lda + (k0) + c4);                        \
        }                                                                        \
        _Pragma("unroll")                                                        \
        for (int i = 0; i < 4; i++) {                                            \
            int idx = tid + i * 256;                                             \
            int row = idx >> 3;                                                  \
            int c4  = (idx & 7) * 4;                                             \
            cp_async16(_bb + (uint32_t)(row * 36 + c4) * 4u,                     \
                       Bg + (long)row * ldb + (k0) + c4);                        \
        }                                                                        \
        cp_commit();                                                             \
    } while (0)

    float acc[4][8][4];
#pragma unroll
    for (int mi = 0; mi < 4; mi++)
#pragma unroll
        for (int ni = 0; ni < 8; ni++)
#pragma unroll
            for (int e = 0; e < 4; e++) acc[mi][ni][e] = 0.0f;

    const int T = K >> 5;

    LOAD_SLAB(0, 0);
    if (T > 1) LOAD_SLAB(1, 32); else cp_commit();

    for (int t = 0; t < T; t++) {
        cp_wait1();           // slab t landed
        __syncthreads();

        const float* Asb = Asf[t % 3];
        const float* Bsb = Bsf[t % 3];

#pragma unroll
        for (int ks = 0; ks < 32; ks += 8) {
            unsigned a[4][4], b[8][2];
#pragma unroll
            for (int mi = 0; mi < 4; mi++) {
                const float* ap = &Asb[(wm + mi * 16 + qr) * 36 + ks + qc];
                a[mi][0] = __float_as_uint(ap[0]);
                a[mi][1] = __float_as_uint(ap[8 * 36]);
                a[mi][2] = __float_as_uint(ap[4]);
                a[mi][3] = __float_as_uint(ap[8 * 36 + 4]);
            }
#pragma unroll
            for (int ni = 0; ni < 8; ni++) {
                const float* bp = &Bsb[(wn + ni * 8 + qr) * 36 + ks + qc];
                b[ni][0] = __float_as_uint(bp[0]);
                b[ni][1] = __float_as_uint(bp[4]);
            }
#pragma unroll
            for (int mi = 0; mi < 4; mi++)
#pragma unroll
                for (int ni = 0; ni < 8; ni++) {
                    asm volatile(
                        "mma.sync.aligned.m16n8k8.row.col.f32.tf32.tf32.f32 "
                        "{%0,%1,%2,%3}, {%4,%5,%6,%7}, {%8,%9}, {%0,%1,%2,%3};"
                        : "+f"(acc[mi][ni][0]), "+f"(acc[mi][ni][1]),
                          "+f"(acc[mi][ni][2]), "+f"(acc[mi][ni][3])
                        : "r"(a[mi][0]), "r"(a[mi][1]), "r"(a[mi][2]), "r"(a[mi][3]),
                          "r"(b[ni][0]), "r"(b[ni][1]));
                }
        }
        __syncthreads();      // buffer t%3 free for reuse
        if (t + 2 < T) LOAD_SLAB((t + 2) % 3, (t + 2) << 5);
    }

    // ---- epilogue ----
    float* Cg = C + (long)bz * sC + (long)bm * 256 * ldc + (long)bn * 128;
#pragma unroll
    for (int ni = 0; ni < 8; ni++) {
        int col = wn + ni * 8 + qc * 2;
        float b0 = bias ? bias[(long)bn * 128 + col]     : 0.0f;
        float b1 = bias ? bias[(long)bn * 128 + col + 1] : 0.0f;
#pragma unroll
        for (int mi = 0; mi < 4; mi++) {
            int row = wm + mi * 16 + qr;
            float t0 = acc[mi][ni][0] + b0;
            float t1 = acc[mi][ni][1] + b1;
            float t2 = acc[mi][ni][2] + b0;
            float t3 = acc[mi][ni][3] + b1;
            if (act == 1) {
                t0 = gelu_tanh(t0); t1 = gelu_tanh(t1);
                t2 = gelu_tanh(t2); t3 = gelu_tanh(t3);
            }
            *(float2*)(Cg + (long)row * ldc + col)       = make_float2(t0, t1);
            *(float2*)(Cg + (long)(row + 8) * ldc + col) = make_float2(t2, t3);
        }
    }
    #undef LOAD_SLAB
}

// ---------------- LN + modulation: x_mod = (1+scale)*LN(x) + shift --------------
__global__ void ln_mod_kernel(const float* __restrict__ txt_emb,
                              const float* __restrict__ img_emb,
                              const float* __restrict__ tsc, const float* __restrict__ tsh,
                              const float* __restrict__ isc, const float* __restrict__ ish)
{
    int l = blockIdx.x, tid = threadIdx.x;
    __shared__ float row[DIMC];
    __shared__ float redA[8], redB[8];

    const float *x, *sc, *sh;
    if (l < L_TXTC) { x = txt_emb + (long)l * DIMC; sc = tsc; sh = tsh; }
    else            { x = img_emb + (long)(l - L_TXTC) * DIMC; sc = isc; sh = ish; }

    float s = 0.f, s2 = 0.f;
    for (int i = tid; i < DIMC; i += 256) {
        float v = x[i]; row[i] = v; s += v; s2 += v * v;
    }
#pragma unroll
    for (int o = 16; o > 0; o >>= 1) {
        s  += __shfl_xor_sync(0xffffffffu, s,  o);
        s2 += __shfl_xor_sync(0xffffffffu, s2, o);
    }
    int w = tid >> 5;
    if ((tid & 31) == 0) { redA[w] = s; redB[w] = s2; }
    __syncthreads();
    if (tid == 0) {
        float a = 0.f, b = 0.f;
        for (int i = 0; i < 8; i++) { a += redA[i]; b += redB[i]; }
        redA[0] = a; redB[0] = b;
    }
    __syncthreads();
    float mean = redA[0] / DIMC;
    float var  = redB[0] / DIMC - mean * mean;
    float rstd = rsqrtf(var + 1e-6f);

    float* out = g_xmod + (long)l * DIMC;
    for (int i = tid; i < DIMC; i += 256)
        out[i] = (1.0f + sc[i]) * ((row[i] - mean) * rstd) + sh[i];
}

// ---------------- QKV post: RMSNorm + RoPE + scale + transpose ------------------
__global__ void qkv_post_kernel(const float* __restrict__ pe,
                                const float* __restrict__ tqw,
                                const float* __restrict__ iqw)
{
    int l = blockIdx.x, h = blockIdx.y, d = threadIdx.x;
    const float* base = g_qkv + (long)l * QKVD + h * DHC;
    float qv = base[d];
    float kv = base[DIMC + d];
    float vv = base[2 * DIMC + d];
    const float* w = (l < L_TXTC) ? tqw : iqw;

    __shared__ float s1[DHC], s2[DHC], sq[DHC], sk[DHC];
    s1[d] = qv * qv; s2[d] = kv * kv;
    __syncthreads();
    for (int o = 64; o > 0; o >>= 1) {
        if (d < o) { s1[d] += s1[d + o]; s2[d] += s2[d + o]; }
        __syncthreads();
    }
    float rq = rsqrtf(s1[0] / DHC + 1e-6f);
    float rk = rsqrtf(s2[0] / DHC + 1e-6f);
    __syncthreads();
    sq[d] = qv * rq * w[d];
    sk[d] = kv * rk * w[d];
    __syncthreads();

    int j = d >> 1;
    float c = pe[(long)l * 256 + j * 4];
    float s = pe[(long)l * 256 + j * 4 + 2];
    float qr, kr;
    if ((d & 1) == 0) {
        qr = sq[d] * c - sq[d + 1] * s;
        kr = sk[d] * c - sk[d + 1] * s;
    } else {
        qr = sq[d - 1] * s + sq[d] * c;
        kr = sk[d - 1] * s + sk[d] * c;
    }
    long qi = ((long)h * L_ALLC + l) * DHC + d;
    g_q[qi] = qr * 0.08838834764831845f;  // DH^-0.5 folded into q
    g_k[qi] = kr;
    g_vt[((long)h * DHC + d) * L_ALLC + l] = vv;
}

// ---------------- softmax over rows of S (mask is all-true) ---------------------
__global__ void softmax_kernel()
{
    float* S = g_S + ((long)blockIdx.y * L_ALLC + blockIdx.x) * L_ALLC;
    int tid = threadIdx.x;
    __shared__ float redA[8], redB[8];

    float v[8];
#pragma unroll
    for (int i = 0; i < 8; i++) v[i] = S[tid + i * 256];

    float m = v[0];
#pragma unroll
    for (int i = 1; i < 8; i++) m = fmaxf(m, v[i]);
#pragma unroll
    for (int o = 16; o > 0; o >>= 1) m = fmaxf(m, __shfl_xor_sync(0xffffffffu, m, o));
    int w = tid >> 5;
    if ((tid & 31) == 0) redA[w] = m;
    __syncthreads();
    if (tid == 0) {
        float t = redA[0];
        for (int i = 1; i < 8; i++) t = fmaxf(t, redA[i]);
        redA[0] = t;
    }
    __syncthreads();
    m = redA[0];

    float sum = 0.f;
#pragma unroll
    for (int i = 0; i < 8; i++) { v[i] = __expf(v[i] - m); sum += v[i]; }
#pragma unroll
    for (int o = 16; o > 0; o >>= 1) sum += __shfl_xor_sync(0xffffffffu, sum, o);
    if ((tid & 31) == 0) redB[w] = sum;
    __syncthreads();
    if (tid == 0) {
        float t = 0.f;
        for (int i = 0; i < 8; i++) t += redB[i];
        redB[0] = t;
    }
    __syncthreads();
    float inv = 1.0f / redB[0];
#pragma unroll
    for (int i = 0; i < 8; i++) S[tid + i * 256] = v[i] * inv;
}

// ---------------- residual + LN + MLP modulation --------------------------------
__global__ void res_ln_kernel(const float* __restrict__ txt_emb,
                              const float* __restrict__ img_emb,
                              const float* __restrict__ tgate, const float* __restrict__ igate,
                              const float* __restrict__ tmsc,  const float* __restrict__ tmsh,
                              const float* __restrict__ imsc,  const float* __restrict__ imsh)
{
    int l = blockIdx.x, tid = threadIdx.x;
    __shared__ float row[DIMC];
    __shared__ float redA[8], redB[8];

    const float *emb, *gate, *msc, *msh;
    if (l < L_TXTC) { emb = txt_emb + (long)l * DIMC; gate = tgate; msc = tmsc; msh = tmsh; }
    else            { emb = img_emb + (long)(l - L_TXTC) * DIMC; gate = igate; msc = imsc; msh = imsh; }

    const float* attn = g_attno + (long)l * DIMC;
    float* xres = g_xres + (long)l * DIMC;

    float s = 0.f, s2 = 0.f;
    for (int i = tid; i < DIMC; i += 256) {
        float v = emb[i] + gate[i] * attn[i];
        row[i] = v; xres[i] = v; s += v; s2 += v * v;
    }
#pragma unroll
    for (int o = 16; o > 0; o >>= 1) {
        s  += __shfl_xor_sync(0xffffffffu, s,  o);
        s2 += __shfl_xor_sync(0xffffffffu, s2, o);
    }
    int w = tid >> 5;
    if ((tid & 31) == 0) { redA[w] = s; redB[w] = s2; }
    __syncthreads();
    if (tid == 0) {
        float a = 0.f, b = 0.f;
        for (int i = 0; i < 8; i++) { a += redA[i]; b += redB[i]; }
        redA[0] = a; redB[0] = b;
    }
    __syncthreads();
    float mean = redA[0] / DIMC;
    float var  = redB[0] / DIMC - mean * mean;
    float rstd = rsqrtf(var + 1e-6f);

    float* out = g_mlpin + (long)l * DIMC;
    for (int i = tid; i < DIMC; i += 256)
        out[i] = (1.0f + msc[i]) * ((row[i] - mean) * rstd) + msh[i];
}

// ---------------- final residual + output assembly (img first, then txt) --------
__global__ void final_kernel(float* __restrict__ out,
                             const float* __restrict__ tgate,
                             const float* __restrict__ igate)
{
    int l = blockIdx.x, tid = threadIdx.x;
    const float* g;
    float* dst;
    if (l < L_TXTC) { g = tgate; dst = out + (long)L_IMGC * DIMC + (long)l * DIMC; }
    else            { g = igate; dst = out + (long)(l - L_TXTC) * DIMC; }
    const float* xr = g_xres + (long)l * DIMC;
    const float* mo = g_mlpo + (long)l * DIMC;
    for (int i = tid; i < DIMC; i += 256)
        dst[i] = xr[i] + g[i] * mo[i];
}

// ---------------- host ----------------------------------------------------------
static void sgemm(const float* A, long lda, long sA,
                  const float* B, long ldb, long sB,
                  const float* bias,
                  float* C, long ldc, long sC,
                  int M, int N, int K, int batch, int act)
{
    dim3 grid((M / 256) * (N / 128), 1, batch);
    gemm_tf32_kernel<<<grid, 256, GSMEM_BYTES>>>(A, lda, sA, B, ldb, sB, bias,
                                                 C, ldc, sC, M, K, act);
}

extern "C" void kernel_launch(void* const* d_in, const int* in_sizes, int n_in,
                              void* d_out, int out_size)
{
    cudaFuncSetAttribute(gemm_tf32_kernel,
                         cudaFuncAttributeMaxDynamicSharedMemorySize, GSMEM_BYTES);

    const float* img_emb   = (const float*)d_in[0];
    const float* txt_emb   = (const float*)d_in[1];
    const float* pe        = (const float*)d_in[2];
    const float* i_asc = (const float*)d_in[3];
    const float* i_ash = (const float*)d_in[4];
    const float* i_ag  = (const float*)d_in[5];
    const float* i_msc = (const float*)d_in[6];
    const float* i_msh = (const float*)d_in[7];
    const float* i_mg  = (const float*)d_in[8];
    const float* t_asc = (const float*)d_in[9];
    const float* t_ash = (const float*)d_in[10];
    const float* t_ag  = (const float*)d_in[11];
    const float* t_msc = (const float*)d_in[12];
    const float* t_msh = (const float*)d_in[13];
    const float* t_mg  = (const float*)d_in[14];
    const float* i_qkv_w = (const float*)d_in[15];
    const float* i_qkv_b = (const float*)d_in[16];
    const float* i_qnw   = (const float*)d_in[17];
    const float* t_qkv_w = (const float*)d_in[18];
    const float* t_qkv_b = (const float*)d_in[19];
    const float* t_qnw   = (const float*)d_in[20];
    const float* proj_w  = (const float*)d_in[21];
    const float* proj_b  = (const float*)d_in[22];
    const float* i_w1 = (const float*)d_in[23];
    const float* i_b1 = (const float*)d_in[24];
    const float* i_w2 = (const float*)d_in[25];
    const float* i_b2 = (const float*)d_in[26];
    const float* t_w1 = (const float*)d_in[27];
    const float* t_b1 = (const float*)d_in[28];
    const float* t_w2 = (const float*)d_in[29];
    const float* t_b2 = (const float*)d_in[30];
    // d_in[31] = mask: all-true in this problem -> no-op in softmax.

    float *p_xmod, *p_qkv, *p_q, *p_k, *p_vt, *p_S, *p_ocat, *p_attno, *p_mlpin, *p_hid, *p_mlpo;
    cudaGetSymbolAddress((void**)&p_xmod,  g_xmod);
    cudaGetSymbolAddress((void**)&p_qkv,   g_qkv);
    cudaGetSymbolAddress((void**)&p_q,     g_q);
    cudaGetSymbolAddress((void**)&p_k,     g_k);
    cudaGetSymbolAddress((void**)&p_vt,    g_vt);
    cudaGetSymbolAddress((void**)&p_S,     g_S);
    cudaGetSymbolAddress((void**)&p_ocat,  g_ocat);
    cudaGetSymbolAddress((void**)&p_attno, g_attno);
    cudaGetSymbolAddress((void**)&p_mlpin, g_mlpin);
    cudaGetSymbolAddress((void**)&p_hid,   g_hid);
    cudaGetSymbolAddress((void**)&p_mlpo,  g_mlpo);

    float* out = (float*)d_out;

    // 1. LN + attn modulation -> g_xmod (txt rows 0..511, img rows 512..2047)
    ln_mod_kernel<<<L_ALLC, 256>>>(txt_emb, img_emb, t_asc, t_ash, i_asc, i_ash);

    // 2/3. QKV GEMMs
    sgemm(p_xmod, DIMC, 0, t_qkv_w, DIMC, 0, t_qkv_b,
          p_qkv, QKVD, 0, L_TXTC, QKVD, DIMC, 1, 0);
    sgemm(p_xmod + (long)L_TXTC * DIMC, DIMC, 0, i_qkv_w, DIMC, 0, i_qkv_b,
          p_qkv + (long)L_TXTC * QKVD, QKVD, 0, L_IMGC, QKVD, DIMC, 1, 0);

    // 4. RMSNorm + RoPE + scale + layout
    {
        dim3 grid(L_ALLC, NH);
        qkv_post_kernel<<<grid, DHC>>>(pe, t_qnw, i_qnw);
    }

    // 5. scores = q @ k^T (batched over heads)
    sgemm(p_q, DHC, (long)L_ALLC * DHC, p_k, DHC, (long)L_ALLC * DHC, nullptr,
          p_S, L_ALLC, (long)L_ALLC * L_ALLC, L_ALLC, L_ALLC, DHC, NH, 0);

    // 6. softmax
    {
        dim3 grid(L_ALLC, NH);
        softmax_kernel<<<grid, 256>>>();
    }

    // 7. o = attn @ v  -> written directly into concatenated layout g_ocat
    sgemm(p_S, L_ALLC, (long)L_ALLC * L_ALLC, p_vt, L_ALLC, (long)DHC * L_ALLC, nullptr,
          p_ocat, DIMC, DHC, L_ALLC, DHC, L_ALLC, NH, 0);

    // 8. shared proj
    sgemm(p_ocat, DIMC, 0, proj_w, DIMC, 0, proj_b,
          p_attno, DIMC, 0, L_ALLC, DIMC, DIMC, 1, 0);

    // 9. residual + LN + mlp modulation
    res_ln_kernel<<<L_ALLC, 256>>>(txt_emb, img_emb, t_ag, i_ag, t_msc, t_msh, i_msc, i_msh);

    // 10/11. MLP up + GELU
    sgemm(p_mlpin, DIMC, 0, t_w1, DIMC, 0, t_b1,
          p_hid, MLPD, 0, L_TXTC, MLPD, DIMC, 1, 1);
    sgemm(p_mlpin + (long)L_TXTC * DIMC, DIMC, 0, i_w1, DIMC, 0, i_b1,
          p_hid + (long)L_TXTC * MLPD, MLPD, 0, L_IMGC, MLPD, DIMC, 1, 1);

    // 12/13. MLP down
    sgemm(p_hid, MLPD, 0, t_w2, MLPD, 0, t_b2,
          p_mlpo, DIMC, 0, L_TXTC, DIMC, MLPD, 1, 0);
    sgemm(p_hid + (long)L_TXTC * MLPD, MLPD, 0, i_w2, MLPD, 0, i_b2,
          p_mlpo + (long)L_TXTC * DIMC, DIMC, 0, L_IMGC, DIMC, MLPD, 1, 0);

    // 14. final residual + write output (img block first, then txt block)
    final_kernel<<<L_ALLC, 256>>>(out, t_mg, i_mg);
}

// round 6
// speedup vs baseline: 1.1026x; 1.1026x over previous
#include <cuda_runtime.h>
#include <math.h>
#include <stdint.h>

#define L_ALLC 2048
#define L_TXTC 512
#define L_IMGC 1536
#define NH     24
#define DHC    128
#define DIMC   3072
#define QKVD   9216
#define MLPD   12288

// ---------------- scratch (device globals; no runtime allocation) ----------------
__device__ float g_xmod  [L_ALLC * DIMC];
__device__ float g_qkv   [L_ALLC * QKVD];
__device__ float g_q     [NH * L_ALLC * DHC];
__device__ float g_k     [NH * L_ALLC * DHC];
__device__ float g_vt    [NH * DHC * L_ALLC];
__device__ float g_S     [(size_t)NH * L_ALLC * L_ALLC];
__device__ float g_ocat  [L_ALLC * DIMC];
__device__ float g_attno [L_ALLC * DIMC];
__device__ float g_xres  [L_ALLC * DIMC];
__device__ float g_mlpin [L_ALLC * DIMC];
__device__ float g_hid   [L_ALLC * MLPD];
__device__ float g_mlpo  [L_ALLC * DIMC];

__device__ __forceinline__ float gelu_tanh(float x) {
    float x3 = x * x * x;
    return 0.5f * x * (1.0f + tanhf(0.7978845608028654f * (x + 0.044715f * x3)));
}

__device__ __forceinline__ void cp_async16(uint32_t smem_addr, const void* gptr) {
    asm volatile("cp.async.cg.shared.global [%0], [%1], 16;\n"
                 :: "r"(smem_addr), "l"(gptr));
}
__device__ __forceinline__ void cp_commit() {
    asm volatile("cp.async.commit_group;\n");
}
__device__ __forceinline__ void cp_wait2() {
    asm volatile("cp.async.wait_group 2;\n");
}

// ---------------- tf32 mma GEMM, 128x128 CTA tile, 3-stage cp.async --------------
// C = A(MxK) * B(NxK)^T + bias, opt GELU. 256 threads (8 warps 2x4),
// warp tile 64x32, mma.m16n8k8.tf32 (raw fp32 bits; HW truncates mantissa).
// Smem row stride 36 -> conflict-free fragment gathers.
// grid.x decoded M-FASTEST: concurrent CTAs share the same B (weight) tile in L2.
#define SLAB_F   (128 * 36)
#define STAGE_F  (2 * SLAB_F)
#define GSMEM_BYTES (3 * STAGE_F * 4)

__global__ __launch_bounds__(256, 2)
void gemm_tf32_kernel(const float* __restrict__ A, long lda, long sA,
                      const float* __restrict__ B, long ldb, long sB,
                      const float* __restrict__ bias,
                      float* __restrict__ C, long ldc, long sC,
                      int M, int K, int act)
{
    extern __shared__ float sm[];

    const int tid = threadIdx.x;
    const int nm = M >> 7;
    const int bm = blockIdx.x % nm;     // M fastest
    const int bn = blockIdx.x / nm;
    const int bz = blockIdx.z;

    const float* Ag = A + (long)bz * sA + (long)bm * 128 * lda;
    const float* Bg = B + (long)bz * sB + (long)bn * 128 * ldb;

    const int lane = tid & 31, warp = tid >> 5;
    const int wm = (warp >> 2) * 64;
    const int wn = (warp & 3) * 32;
    const int qr = lane >> 2, qc = lane & 3;

    float* Asf[3];
    float* Bsf[3];
    uint32_t Asa[3], Bsa[3];
#pragma unroll
    for (int s = 0; s < 3; s++) {
        Asf[s] = sm + s * STAGE_F;
        Bsf[s] = Asf[s] + SLAB_F;
        Asa[s] = (uint32_t)__cvta_generic_to_shared(Asf[s]);
        Bsa[s] = (uint32_t)__cvta_generic_to_shared(Bsf[s]);
    }

    // producer: one BK=32 slab (A,B: 128x32), 4+4 float4 per thread (no commit)
    #define LOAD_SLAB(s, k0)                                                     \
    do {                                                                         \
        uint32_t _ab = Asa[s], _bb = Bsa[s];                                     \
        _Pragma("unroll")                                                        \
        for (int i = 0; i < 4; i++) {                                            \
            int idx = tid + i * 256;                                             \
            int row = idx >> 3;                                                  \
            int c4  = (idx & 7) * 4;                                             \
            uint32_t off = (uint32_t)(row * 36 + c4) * 4u;                       \
            cp_async16(_ab + off, Ag + (long)row * lda + (k0) + c4);             \
            cp_async16(_bb + off, Bg + (long)row * ldb + (k0) + c4);             \
        }                                                                        \
    } while (0)

    float acc[4][4][4];
#pragma unroll
    for (int mi = 0; mi < 4; mi++)
#pragma unroll
        for (int ni = 0; ni < 4; ni++)
#pragma unroll
            for (int e = 0; e < 4; e++) acc[mi][ni][e] = 0.0f;

    const int T = K >> 5;   // K >= 128 in all call sites -> T >= 4

    LOAD_SLAB(0, 0);
    cp_commit();
    LOAD_SLAB(1, 32);
    cp_commit();

    for (int t = 0; t < T; t++) {
        if (t + 2 < T) LOAD_SLAB((t + 2) % 3, (t + 2) << 5);
        cp_commit();          // uniform one group per iteration
        cp_wait2();           // groups <= t complete -> slab t landed
        __syncthreads();

        const float* Asb = Asf[t % 3];
        const float* Bsb = Bsf[t % 3];

#pragma unroll
        for (int ks = 0; ks < 32; ks += 8) {
            unsigned a[4][4], b[4][2];
#pragma unroll
            for (int mi = 0; mi < 4; mi++) {
                const float* ap = &Asb[(wm + mi * 16 + qr) * 36 + ks + qc];
                a[mi][0] = __float_as_uint(ap[0]);
                a[mi][1] = __float_as_uint(ap[8 * 36]);
                a[mi][2] = __float_as_uint(ap[4]);
                a[mi][3] = __float_as_uint(ap[8 * 36 + 4]);
            }
#pragma unroll
            for (int ni = 0; ni < 4; ni++) {
                const float* bp = &Bsb[(wn + ni * 8 + qr) * 36 + ks + qc];
                b[ni][0] = __float_as_uint(bp[0]);
                b[ni][1] = __float_as_uint(bp[4]);
            }
#pragma unroll
            for (int mi = 0; mi < 4; mi++)
#pragma unroll
                for (int ni = 0; ni < 4; ni++) {
                    asm volatile(
                        "mma.sync.aligned.m16n8k8.row.col.f32.tf32.tf32.f32 "
                        "{%0,%1,%2,%3}, {%4,%5,%6,%7}, {%8,%9}, {%0,%1,%2,%3};"
                        : "+f"(acc[mi][ni][0]), "+f"(acc[mi][ni][1]),
                          "+f"(acc[mi][ni][2]), "+f"(acc[mi][ni][3])
                        : "r"(a[mi][0]), "r"(a[mi][1]), "r"(a[mi][2]), "r"(a[mi][3]),
                          "r"(b[ni][0]), "r"(b[ni][1]));
                }
        }
        __syncthreads();      // buffer t%3 free before iteration t+1 refills it
    }

    // ---- epilogue ----
    float* Cg = C + (long)bz * sC + (long)bm * 128 * ldc + (long)bn * 128;
#pragma unroll
    for (int ni = 0; ni < 4; ni++) {
        int col = wn + ni * 8 + qc * 2;
        float b0 = bias ? bias[(long)bn * 128 + col]     : 0.0f;
        float b1 = bias ? bias[(long)bn * 128 + col + 1] : 0.0f;
#pragma unroll
        for (int mi = 0; mi < 4; mi++) {
            int row = wm + mi * 16 + qr;
            float t0 = acc[mi][ni][0] + b0;
            float t1 = acc[mi][ni][1] + b1;
            float t2 = acc[mi][ni][2] + b0;
            float t3 = acc[mi][ni][3] + b1;
            if (act == 1) {
                t0 = gelu_tanh(t0); t1 = gelu_tanh(t1);
                t2 = gelu_tanh(t2); t3 = gelu_tanh(t3);
            }
            *(float2*)(Cg + (long)row * ldc + col)       = make_float2(t0, t1);
            *(float2*)(Cg + (long)(row + 8) * ldc + col) = make_float2(t2, t3);
        }
    }
    #undef LOAD_SLAB
}

// ---------------- LN + modulation: x_mod = (1+scale)*LN(x) + shift --------------
__global__ void ln_mod_kernel(const float* __restrict__ txt_emb,
                              const float* __restrict__ img_emb,
                              const float* __restrict__ tsc, const float* __restrict__ tsh,
                              const float* __restrict__ isc, const float* __restrict__ ish)
{
    int l = blockIdx.x, tid = threadIdx.x;
    __shared__ float row[DIMC];
    __shared__ float redA[8], redB[8];

    const float *x, *sc, *sh;
    if (l < L_TXTC) { x = txt_emb + (long)l * DIMC; sc = tsc; sh = tsh; }
    else            { x = img_emb + (long)(l - L_TXTC) * DIMC; sc = isc; sh = ish; }

    float s = 0.f, s2 = 0.f;
    for (int i = tid; i < DIMC; i += 256) {
        float v = x[i]; row[i] = v; s += v; s2 += v * v;
    }
#pragma unroll
    for (int o = 16; o > 0; o >>= 1) {
        s  += __shfl_xor_sync(0xffffffffu, s,  o);
        s2 += __shfl_xor_sync(0xffffffffu, s2, o);
    }
    int w = tid >> 5;
    if ((tid & 31) == 0) { redA[w] = s; redB[w] = s2; }
    __syncthreads();
    if (tid == 0) {
        float a = 0.f, b = 0.f;
        for (int i = 0; i < 8; i++) { a += redA[i]; b += redB[i]; }
        redA[0] = a; redB[0] = b;
    }
    __syncthreads();
    float mean = redA[0] / DIMC;
    float var  = redB[0] / DIMC - mean * mean;
    float rstd = rsqrtf(var + 1e-6f);

    float* out = g_xmod + (long)l * DIMC;
    for (int i = tid; i < DIMC; i += 256)
        out[i] = (1.0f + sc[i]) * ((row[i] - mean) * rstd) + sh[i];
}

// ---------------- QKV post: RMSNorm + RoPE + scale + transpose ------------------
__global__ void qkv_post_kernel(const float* __restrict__ pe,
                                const float* __restrict__ tqw,
                                const float* __restrict__ iqw)
{
    int l = blockIdx.x, h = blockIdx.y, d = threadIdx.x;
    const float* base = g_qkv + (long)l * QKVD + h * DHC;
    float qv = base[d];
    float kv = base[DIMC + d];
    float vv = base[2 * DIMC + d];
    const float* w = (l < L_TXTC) ? tqw : iqw;

    __shared__ float s1[DHC], s2[DHC], sq[DHC], sk[DHC];
    s1[d] = qv * qv; s2[d] = kv * kv;
    __syncthreads();
    for (int o = 64; o > 0; o >>= 1) {
        if (d < o) { s1[d] += s1[d + o]; s2[d] += s2[d + o]; }
        __syncthreads();
    }
    float rq = rsqrtf(s1[0] / DHC + 1e-6f);
    float rk = rsqrtf(s2[0] / DHC + 1e-6f);
    __syncthreads();
    sq[d] = qv * rq * w[d];
    sk[d] = kv * rk * w[d];
    __syncthreads();

    int j = d >> 1;
    float c = pe[(long)l * 256 + j * 4];
    float s = pe[(long)l * 256 + j * 4 + 2];
    float qr, kr;
    if ((d & 1) == 0) {
        qr = sq[d] * c - sq[d + 1] * s;
        kr = sk[d] * c - sk[d + 1] * s;
    } else {
        qr = sq[d - 1] * s + sq[d] * c;
        kr = sk[d - 1] * s + sk[d] * c;
    }
    long qi = ((long)h * L_ALLC + l) * DHC + d;
    g_q[qi] = qr * 0.08838834764831845f;  // DH^-0.5 folded into q
    g_k[qi] = kr;
    g_vt[((long)h * DHC + d) * L_ALLC + l] = vv;
}

// ---------------- softmax over rows of S (mask is all-true) ---------------------
__global__ void softmax_kernel()
{
    float* S = g_S + ((long)blockIdx.y * L_ALLC + blockIdx.x) * L_ALLC;
    int tid = threadIdx.x;
    __shared__ float redA[8], redB[8];

    float v[8];
#pragma unroll
    for (int i = 0; i < 8; i++) v[i] = S[tid + i * 256];

    float m = v[0];
#pragma unroll
    for (int i = 1; i < 8; i++) m = fmaxf(m, v[i]);
#pragma unroll
    for (int o = 16; o > 0; o >>= 1) m = fmaxf(m, __shfl_xor_sync(0xffffffffu, m, o));
    int w = tid >> 5;
    if ((tid & 31) == 0) redA[w] = m;
    __syncthreads();
    if (tid == 0) {
        float t = redA[0];
        for (int i = 1; i < 8; i++) t = fmaxf(t, redA[i]);
        redA[0] = t;
    }
    __syncthreads();
    m = redA[0];

    float sum = 0.f;
#pragma unroll
    for (int i = 0; i < 8; i++) { v[i] = __expf(v[i] - m); sum += v[i]; }
#pragma unroll
    for (int o = 16; o > 0; o >>= 1) sum += __shfl_xor_sync(0xffffffffu, sum, o);
    if ((tid & 31) == 0) redB[w] = sum;
    __syncthreads();
    if (tid == 0) {
        float t = 0.f;
        for (int i = 0; i < 8; i++) t += redB[i];
        redB[0] = t;
    }
    __syncthreads();
    float inv = 1.0f / redB[0];
#pragma unroll
    for (int i = 0; i < 8; i++) S[tid + i * 256] = v[i] * inv;
}

// ---------------- residual + LN + MLP modulation --------------------------------
__global__ void res_ln_kernel(const float* __restrict__ txt_emb,
                              const float* __restrict__ img_emb,
                              const float* __restrict__ tgate, const float* __restrict__ igate,
                              const float* __restrict__ tmsc,  const float* __restrict__ tmsh,
                              const float* __restrict__ imsc,  const float* __restrict__ imsh)
{
    int l = blockIdx.x, tid = threadIdx.x;
    __shared__ float row[DIMC];
    __shared__ float redA[8], redB[8];

    const float *emb, *gate, *msc, *msh;
    if (l < L_TXTC) { emb = txt_emb + (long)l * DIMC; gate = tgate; msc = tmsc; msh = tmsh; }
    else            { emb = img_emb + (long)(l - L_TXTC) * DIMC; gate = igate; msc = imsc; msh = imsh; }

    const float* attn = g_attno + (long)l * DIMC;
    float* xres = g_xres + (long)l * DIMC;

    float s = 0.f, s2 = 0.f;
    for (int i = tid; i < DIMC; i += 256) {
        float v = emb[i] + gate[i] * attn[i];
        row[i] = v; xres[i] = v; s += v; s2 += v * v;
    }
#pragma unroll
    for (int o = 16; o > 0; o >>= 1) {
        s  += __shfl_xor_sync(0xffffffffu, s,  o);
        s2 += __shfl_xor_sync(0xffffffffu, s2, o);
    }
    int w = tid >> 5;
    if ((tid & 31) == 0) { redA[w] = s; redB[w] = s2; }
    __syncthreads();
    if (tid == 0) {
        float a = 0.f, b = 0.f;
        for (int i = 0; i < 8; i++) { a += redA[i]; b += redB[i]; }
        redA[0] = a; redB[0] = b;
    }
    __syncthreads();
    float mean = redA[0] / DIMC;
    float var  = redB[0] / DIMC - mean * mean;
    float rstd = rsqrtf(var + 1e-6f);

    float* out = g_mlpin + (long)l * DIMC;
    for (int i = tid; i < DIMC; i += 256)
        out[i] = (1.0f + msc[i]) * ((row[i] - mean) * rstd) + msh[i];
}

// ---------------- final residual + output assembly (img first, then txt) --------
__global__ void final_kernel(float* __restrict__ out,
                             const float* __restrict__ tgate,
                             const float* __restrict__ igate)
{
    int l = blockIdx.x, tid = threadIdx.x;
    const float* g;
    float* dst;
    if (l < L_TXTC) { g = tgate; dst = out + (long)L_IMGC * DIMC + (long)l * DIMC; }
    else            { g = igate; dst = out + (long)(l - L_TXTC) * DIMC; }
    const float* xr = g_xres + (long)l * DIMC;
    const float* mo = g_mlpo + (long)l * DIMC;
    for (int i = tid; i < DIMC; i += 256)
        dst[i] = xr[i] + g[i] * mo[i];
}

// ---------------- host ----------------------------------------------------------
static void sgemm(const float* A, long lda, long sA,
                  const float* B, long ldb, long sB,
                  const float* bias,
                  float* C, long ldc, long sC,
                  int M, int N, int K, int batch, int act)
{
    dim3 grid((M / 128) * (N / 128), 1, batch);
    gemm_tf32_kernel<<<grid, 256, GSMEM_BYTES>>>(A, lda, sA, B, ldb, sB, bias,
                                                 C, ldc, sC, M, K, act);
}

extern "C" void kernel_launch(void* const* d_in, const int* in_sizes, int n_in,
                              void* d_out, int out_size)
{
    cudaFuncSetAttribute(gemm_tf32_kernel,
                         cudaFuncAttributeMaxDynamicSharedMemorySize, GSMEM_BYTES);

    const float* img_emb   = (const float*)d_in[0];
    const float* txt_emb   = (const float*)d_in[1];
    const float* pe        = (const float*)d_in[2];
    const float* i_asc = (const float*)d_in[3];
    const float* i_ash = (const float*)d_in[4];
    const float* i_ag  = (const float*)d_in[5];
    const float* i_msc = (const float*)d_in[6];
    const float* i_msh = (const float*)d_in[7];
    const float* i_mg  = (const float*)d_in[8];
    const float* t_asc = (const float*)d_in[9];
    const float* t_ash = (const float*)d_in[10];
    const float* t_ag  = (const float*)d_in[11];
    const float* t_msc = (const float*)d_in[12];
    const float* t_msh = (const float*)d_in[13];
    const float* t_mg  = (const float*)d_in[14];
    const float* i_qkv_w = (const float*)d_in[15];
    const float* i_qkv_b = (const float*)d_in[16];
    const float* i_qnw   = (const float*)d_in[17];
    const float* t_qkv_w = (const float*)d_in[18];
    const float* t_qkv_b = (const float*)d_in[19];
    const float* t_qnw   = (const float*)d_in[20];
    const float* proj_w  = (const float*)d_in[21];
    const float* proj_b  = (const float*)d_in[22];
    const float* i_w1 = (const float*)d_in[23];
    const float* i_b1 = (const float*)d_in[24];
    const float* i_w2 = (const float*)d_in[25];
    const float* i_b2 = (const float*)d_in[26];
    const float* t_w1 = (const float*)d_in[27];
    const float* t_b1 = (const float*)d_in[28];
    const float* t_w2 = (const float*)d_in[29];
    const float* t_b2 = (const float*)d_in[30];
    // d_in[31] = mask: all-true in this problem -> no-op in softmax.

    float *p_xmod, *p_qkv, *p_q, *p_k, *p_vt, *p_S, *p_ocat, *p_attno, *p_mlpin, *p_hid, *p_mlpo;
    cudaGetSymbolAddress((void**)&p_xmod,  g_xmod);
    cudaGetSymbolAddress((void**)&p_qkv,   g_qkv);
    cudaGetSymbolAddress((void**)&p_q,     g_q);
    cudaGetSymbolAddress((void**)&p_k,     g_k);
    cudaGetSymbolAddress((void**)&p_vt,    g_vt);
    cudaGetSymbolAddress((void**)&p_S,     g_S);
    cudaGetSymbolAddress((void**)&p_ocat,  g_ocat);
    cudaGetSymbolAddress((void**)&p_attno, g_attno);
    cudaGetSymbolAddress((void**)&p_mlpin, g_mlpin);
    cudaGetSymbolAddress((void**)&p_hid,   g_hid);
    cudaGetSymbolAddress((void**)&p_mlpo,  g_mlpo);

    float* out = (float*)d_out;

    // 1. LN + attn modulation -> g_xmod (txt rows 0..511, img rows 512..2047)
    ln_mod_kernel<<<L_ALLC, 256>>>(txt_emb, img_emb, t_asc, t_ash, i_asc, i_ash);

    // 2/3. QKV GEMMs
    sgemm(p_xmod, DIMC, 0, t_qkv_w, DIMC, 0, t_qkv_b,
          p_qkv, QKVD, 0, L_TXTC, QKVD, DIMC, 1, 0);
    sgemm(p_xmod + (long)L_TXTC * DIMC, DIMC, 0, i_qkv_w, DIMC, 0, i_qkv_b,
          p_qkv + (long)L_TXTC * QKVD, QKVD, 0, L_IMGC, QKVD, DIMC, 1, 0);

    // 4. RMSNorm + RoPE + scale + layout
    {
        dim3 grid(L_ALLC, NH);
        qkv_post_kernel<<<grid, DHC>>>(pe, t_qnw, i_qnw);
    }

    // 5. scores = q @ k^T (batched over heads)
    sgemm(p_q, DHC, (long)L_ALLC * DHC, p_k, DHC, (long)L_ALLC * DHC, nullptr,
          p_S, L_ALLC, (long)L_ALLC * L_ALLC, L_ALLC, L_ALLC, DHC, NH, 0);

    // 6. softmax
    {
        dim3 grid(L_ALLC, NH);
        softmax_kernel<<<grid, 256>>>();
    }

    // 7. o = attn @ v  -> written directly into concatenated layout g_ocat
    sgemm(p_S, L_ALLC, (long)L_ALLC * L_ALLC, p_vt, L_ALLC, (long)DHC * L_ALLC, nullptr,
          p_ocat, DIMC, DHC, L_ALLC, DHC, L_ALLC, NH, 0);

    // 8. shared proj
    sgemm(p_ocat, DIMC, 0, proj_w, DIMC, 0, proj_b,
          p_attno, DIMC, 0, L_ALLC, DIMC, DIMC, 1, 0);

    // 9. residual + LN + mlp modulation
    res_ln_kernel<<<L_ALLC, 256>>>(txt_emb, img_emb, t_ag, i_ag, t_msc, t_msh, i_msc, i_msh);

    // 10/11. MLP up + GELU
    sgemm(p_mlpin, DIMC, 0, t_w1, DIMC, 0, t_b1,
          p_hid, MLPD, 0, L_TXTC, MLPD, DIMC, 1, 1);
    sgemm(p_mlpin + (long)L_TXTC * DIMC, DIMC, 0, i_w1, DIMC, 0, i_b1,
          p_hid + (long)L_TXTC * MLPD, MLPD, 0, L_IMGC, MLPD, DIMC, 1, 1);

    // 12/13. MLP down
    sgemm(p_hid, MLPD, 0, t_w2, MLPD, 0, t_b2,
          p_mlpo, DIMC, 0, L_TXTC, DIMC, MLPD, 1, 0);
    sgemm(p_hid + (long)L_TXTC * MLPD, MLPD, 0, i_w2, MLPD, 0, i_b2,
          p_mlpo + (long)L_TXTC * DIMC, DIMC, 0, L_IMGC, DIMC, MLPD, 1, 0);

    // 14. final residual + write output (img block first, then txt block)
    final_kernel<<<L_ALLC, 256>>>(out, t_mg, i_mg);
}

// round 7
// speedup vs baseline: 1.2250x; 1.1110x over previous
#include <cuda_runtime.h>
#include <math.h>
#include <stdint.h>

#define L_ALLC 2048
#define L_TXTC 512
#define L_IMGC 1536
#define NH     24
#define DHC    128
#define DIMC   3072
#define QKVD   9216
#define MLPD   12288

// ---------------- scratch (device globals; no runtime allocation) ----------------
__device__ float g_xmod  [L_ALLC * DIMC];
__device__ float g_qkv   [L_ALLC * QKVD];
__device__ float g_q     [NH * L_ALLC * DHC];
__device__ float g_k     [NH * L_ALLC * DHC];
__device__ float g_vt    [NH * DHC * L_ALLC];
__device__ float g_S     [(size_t)NH * L_ALLC * L_ALLC];
__device__ float g_ocat  [L_ALLC * DIMC];
__device__ float g_attno [L_ALLC * DIMC];
__device__ float g_xres  [L_ALLC * DIMC];
__device__ float g_mlpin [L_ALLC * DIMC];
__device__ float g_hid   [L_ALLC * MLPD];
__device__ float g_mlpo  [L_ALLC * DIMC];

__device__ __forceinline__ float gelu_tanh(float x) {
    float x3 = x * x * x;
    return 0.5f * x * (1.0f + tanhf(0.7978845608028654f * (x + 0.044715f * x3)));
}

__device__ __forceinline__ void cp_async16(unsigned smem_addr, const void* gptr) {
    asm volatile("cp.async.cg.shared.global [%0], [%1], 16;\n"
                 :: "r"(smem_addr), "l"(gptr));
}
__device__ __forceinline__ void cp_commit() {
    asm volatile("cp.async.commit_group;\n");
}
__device__ __forceinline__ void cp_wait1() {
    asm volatile("cp.async.wait_group 1;\n");
}

// ---------------- tf32 mma GEMM, 128x128 CTA tile, static 2-stage cp.async -------
// C = A(MxK) * B(NxK)^T + bias, opt GELU. 256 threads (8 warps 2x4),
// warp tile 64x32, mma.m16n8k8.tf32 (raw fp32 bits; HW truncates mantissa).
// Smem row stride 36 words -> conflict-free fragment gathers.
// 1-D grid decoded M-FASTEST: concurrent CTAs share the same B (weight) tile in L2.
__global__ __launch_bounds__(256, 2)
void gemm_tf32_kernel(const float* __restrict__ A, long lda, long sA,
                      const float* __restrict__ B, long ldb, long sB,
                      const float* __restrict__ bias,
                      float* __restrict__ C, long ldc, long sC,
                      int M, int K, int act)
{
    __shared__ float As[2][128 * 36];
    __shared__ float Bs[2][128 * 36];

    const int tid = threadIdx.x;
    const int nm = M >> 7;
    const int bm = blockIdx.x % nm;     // M fastest -> B tile shared across wave
    const int bn = blockIdx.x / nm;
    const int bz = blockIdx.z;

    const float* Ag = A + (long)bz * sA + (long)bm * 128 * lda;
    const float* Bg = B + (long)bz * sB + (long)bn * 128 * ldb;

    const int lane = tid & 31;
    const int warp = tid >> 5;
    const int wm = (warp >> 2) * 64;
    const int wn = (warp & 3) * 32;
    const int qr = lane >> 2;
    const int qc = lane & 3;

    const int prow[4] = { (tid + 0) >> 3, (tid + 256) >> 3, (tid + 512) >> 3, (tid + 768) >> 3 };
    const int pc4 = (tid & 7) * 4;

    unsigned sAaddr[2], sBaddr[2];
    sAaddr[0] = (unsigned)__cvta_generic_to_shared(&As[0][0]);
    sAaddr[1] = (unsigned)__cvta_generic_to_shared(&As[1][0]);
    sBaddr[0] = (unsigned)__cvta_generic_to_shared(&Bs[0][0]);
    sBaddr[1] = (unsigned)__cvta_generic_to_shared(&Bs[1][0]);

    float acc[4][4][4];
#pragma unroll
    for (int mi = 0; mi < 4; mi++)
#pragma unroll
        for (int ni = 0; ni < 4; ni++)
#pragma unroll
            for (int e = 0; e < 4; e++) acc[mi][ni][e] = 0.0f;

    const int T = K >> 5;

    // prologue: stage 0
#pragma unroll
    for (int r = 0; r < 4; r++) {
        int row = prow[r];
        unsigned off = (unsigned)(row * 36 + pc4) * 4u;
        cp_async16(sAaddr[0] + off, Ag + (long)row * lda + pc4);
        cp_async16(sBaddr[0] + off, Bg + (long)row * ldb + pc4);
    }
    cp_commit();

    for (int t = 0; t < T; t++) {
        if (t + 1 < T) {
            int buf = (t + 1) & 1;
            int k0 = (t + 1) << 5;
#pragma unroll
            for (int r = 0; r < 4; r++) {
                int row = prow[r];
                unsigned off = (unsigned)(row * 36 + pc4) * 4u;
                cp_async16(sAaddr[buf] + off, Ag + (long)row * lda + k0 + pc4);
                cp_async16(sBaddr[buf] + off, Bg + (long)row * ldb + k0 + pc4);
            }
        }
        cp_commit();
        cp_wait1();
        __syncthreads();

        const float* Asb = As[t & 1];
        const float* Bsb = Bs[t & 1];

#pragma unroll
        for (int ks = 0; ks < 32; ks += 8) {
            unsigned a[4][4], b[4][2];
#pragma unroll
            for (int mi = 0; mi < 4; mi++) {
                const float* ap = &Asb[(wm + mi * 16 + qr) * 36 + ks + qc];
                a[mi][0] = __float_as_uint(ap[0]);
                a[mi][1] = __float_as_uint(ap[8 * 36]);
                a[mi][2] = __float_as_uint(ap[4]);
                a[mi][3] = __float_as_uint(ap[8 * 36 + 4]);
            }
#pragma unroll
            for (int ni = 0; ni < 4; ni++) {
                const float* bp = &Bsb[(wn + ni * 8 + qr) * 36 + ks + qc];
                b[ni][0] = __float_as_uint(bp[0]);
                b[ni][1] = __float_as_uint(bp[4]);
            }
#pragma unroll
            for (int mi = 0; mi < 4; mi++)
#pragma unroll
                for (int ni = 0; ni < 4; ni++) {
                    asm volatile(
                        "mma.sync.aligned.m16n8k8.row.col.f32.tf32.tf32.f32 "
                        "{%0,%1,%2,%3}, {%4,%5,%6,%7}, {%8,%9}, {%0,%1,%2,%3};"
                        : "+f"(acc[mi][ni][0]), "+f"(acc[mi][ni][1]),
                          "+f"(acc[mi][ni][2]), "+f"(acc[mi][ni][3])
                        : "r"(a[mi][0]), "r"(a[mi][1]), "r"(a[mi][2]), "r"(a[mi][3]),
                          "r"(b[ni][0]), "r"(b[ni][1]));
                }
        }
        __syncthreads();
    }

    // ---- epilogue ----
    float* Cg = C + (long)bz * sC + (long)bm * 128 * ldc + (long)bn * 128;
#pragma unroll
    for (int ni = 0; ni < 4; ni++) {
        int col = wn + ni * 8 + qc * 2;
        float b0 = bias ? bias[(long)bn * 128 + col]     : 0.0f;
        float b1 = bias ? bias[(long)bn * 128 + col + 1] : 0.0f;
#pragma unroll
        for (int mi = 0; mi < 4; mi++) {
            int row = wm + mi * 16 + qr;
            float t0 = acc[mi][ni][0] + b0;
            float t1 = acc[mi][ni][1] + b1;
            float t2 = acc[mi][ni][2] + b0;
            float t3 = acc[mi][ni][3] + b1;
            if (act == 1) {
                t0 = gelu_tanh(t0); t1 = gelu_tanh(t1);
                t2 = gelu_tanh(t2); t3 = gelu_tanh(t3);
            }
            *(float2*)(Cg + (long)row * ldc + col)       = make_float2(t0, t1);
            *(float2*)(Cg + (long)(row + 8) * ldc + col) = make_float2(t2, t3);
        }
    }
}

// ---------------- LN + modulation: x_mod = (1+scale)*LN(x) + shift --------------
__global__ void ln_mod_kernel(const float* __restrict__ txt_emb,
                              const float* __restrict__ img_emb,
                              const float* __restrict__ tsc, const float* __restrict__ tsh,
                              const float* __restrict__ isc, const float* __restrict__ ish)
{
    int l = blockIdx.x, tid = threadIdx.x;
    __shared__ float row[DIMC];
    __shared__ float redA[8], redB[8];

    const float *x, *sc, *sh;
    if (l < L_TXTC) { x = txt_emb + (long)l * DIMC; sc = tsc; sh = tsh; }
    else            { x = img_emb + (long)(l - L_TXTC) * DIMC; sc = isc; sh = ish; }

    float s = 0.f, s2 = 0.f;
    for (int i = tid; i < DIMC; i += 256) {
        float v = x[i]; row[i] = v; s += v; s2 += v * v;
    }
#pragma unroll
    for (int o = 16; o > 0; o >>= 1) {
        s  += __shfl_xor_sync(0xffffffffu, s,  o);
        s2 += __shfl_xor_sync(0xffffffffu, s2, o);
    }
    int w = tid >> 5;
    if ((tid & 31) == 0) { redA[w] = s; redB[w] = s2; }
    __syncthreads();
    if (tid == 0) {
        float a = 0.f, b = 0.f;
        for (int i = 0; i < 8; i++) { a += redA[i]; b += redB[i]; }
        redA[0] = a; redB[0] = b;
    }
    __syncthreads();
    float mean = redA[0] / DIMC;
    float var  = redB[0] / DIMC - mean * mean;
    float rstd = rsqrtf(var + 1e-6f);

    float* out = g_xmod + (long)l * DIMC;
    for (int i = tid; i < DIMC; i += 256)
        out[i] = (1.0f + sc[i]) * ((row[i] - mean) * rstd) + sh[i];
}

// ---------------- QKV post: RMSNorm + RoPE + scale + transpose ------------------
__global__ void qkv_post_kernel(const float* __restrict__ pe,
                                const float* __restrict__ tqw,
                                const float* __restrict__ iqw)
{
    int l = blockIdx.x, h = blockIdx.y, d = threadIdx.x;
    const float* base = g_qkv + (long)l * QKVD + h * DHC;
    float qv = base[d];
    float kv = base[DIMC + d];
    float vv = base[2 * DIMC + d];
    const float* w = (l < L_TXTC) ? tqw : iqw;

    __shared__ float s1[DHC], s2[DHC], sq[DHC], sk[DHC];
    s1[d] = qv * qv; s2[d] = kv * kv;
    __syncthreads();
    for (int o = 64; o > 0; o >>= 1) {
        if (d < o) { s1[d] += s1[d + o]; s2[d] += s2[d + o]; }
        __syncthreads();
    }
    float rq = rsqrtf(s1[0] / DHC + 1e-6f);
    float rk = rsqrtf(s2[0] / DHC + 1e-6f);
    __syncthreads();
    sq[d] = qv * rq * w[d];
    sk[d] = kv * rk * w[d];
    __syncthreads();

    int j = d >> 1;
    float c = pe[(long)l * 256 + j * 4];
    float s = pe[(long)l * 256 + j * 4 + 2];
    float qr, kr;
    if ((d & 1) == 0) {
        qr = sq[d] * c - sq[d + 1] * s;
        kr = sk[d] * c - sk[d + 1] * s;
    } else {
        qr = sq[d - 1] * s + sq[d] * c;
        kr = sk[d - 1] * s + sk[d] * c;
    }
    long qi = ((long)h * L_ALLC + l) * DHC + d;
    g_q[qi] = qr * 0.08838834764831845f;  // DH^-0.5 folded into q
    g_k[qi] = kr;
    g_vt[((long)h * DHC + d) * L_ALLC + l] = vv;
}

// ---------------- softmax over rows of S: 512 thr, one float4 per thread --------
__global__ __launch_bounds__(512)
void softmax_kernel()
{
    float* S = g_S + ((long)blockIdx.y * L_ALLC + blockIdx.x) * L_ALLC;
    const int tid = threadIdx.x;
    __shared__ float red[16];

    float4 v = *(const float4*)(S + tid * 4);

    float m = fmaxf(fmaxf(v.x, v.y), fmaxf(v.z, v.w));
#pragma unroll
    for (int o = 16; o > 0; o >>= 1) m = fmaxf(m, __shfl_xor_sync(0xffffffffu, m, o));
    int w = tid >> 5;
    if ((tid & 31) == 0) red[w] = m;
    __syncthreads();
    if (tid < 32) {
        float t = (tid < 16) ? red[tid] : -1e30f;
#pragma unroll
        for (int o = 8; o > 0; o >>= 1) t = fmaxf(t, __shfl_xor_sync(0xffffffffu, t, o));
        if (tid == 0) red[0] = t;
    }
    __syncthreads();
    m = red[0];

    v.x = __expf(v.x - m); v.y = __expf(v.y - m);
    v.z = __expf(v.z - m); v.w = __expf(v.w - m);
    float s = v.x + v.y + v.z + v.w;
#pragma unroll
    for (int o = 16; o > 0; o >>= 1) s += __shfl_xor_sync(0xffffffffu, s, o);
    if ((tid & 31) == 0) red[w] = s;
    __syncthreads();
    if (tid < 32) {
        float t = (tid < 16) ? red[tid] : 0.0f;
#pragma unroll
        for (int o = 8; o > 0; o >>= 1) t += __shfl_xor_sync(0xffffffffu, t, o);
        if (tid == 0) red[0] = t;
    }
    __syncthreads();
    float inv = 1.0f / red[0];

    v.x *= inv; v.y *= inv; v.z *= inv; v.w *= inv;
    *(float4*)(S + tid * 4) = v;
}

// ---------------- residual + LN + MLP modulation --------------------------------
__global__ void res_ln_kernel(const float* __restrict__ txt_emb,
                              const float* __restrict__ img_emb,
                              const float* __restrict__ tgate, const float* __restrict__ igate,
                              const float* __restrict__ tmsc,  const float* __restrict__ tmsh,
                              const float* __restrict__ imsc,  const float* __restrict__ imsh)
{
    int l = blockIdx.x, tid = threadIdx.x;
    __shared__ float row[DIMC];
    __shared__ float redA[8], redB[8];

    const float *emb, *gate, *msc, *msh;
    if (l < L_TXTC) { emb = txt_emb + (long)l * DIMC; gate = tgate; msc = tmsc; msh = tmsh; }
    else            { emb = img_emb + (long)(l - L_TXTC) * DIMC; gate = igate; msc = imsc; msh = imsh; }

    const float* attn = g_attno + (long)l * DIMC;
    float* xres = g_xres + (long)l * DIMC;

    float s = 0.f, s2 = 0.f;
    for (int i = tid; i < DIMC; i += 256) {
        float v = emb[i] + gate[i] * attn[i];
        row[i] = v; xres[i] = v; s += v; s2 += v * v;
    }
#pragma unroll
    for (int o = 16; o > 0; o >>= 1) {
        s  += __shfl_xor_sync(0xffffffffu, s,  o);
        s2 += __shfl_xor_sync(0xffffffffu, s2, o);
    }
    int w = tid >> 5;
    if ((tid & 31) == 0) { redA[w] = s; redB[w] = s2; }
    __syncthreads();
    if (tid == 0) {
        float a = 0.f, b = 0.f;
        for (int i = 0; i < 8; i++) { a += redA[i]; b += redB[i]; }
        redA[0] = a; redB[0] = b;
    }
    __syncthreads();
    float mean = redA[0] / DIMC;
    float var  = redB[0] / DIMC - mean * mean;
    float rstd = rsqrtf(var + 1e-6f);

    float* out = g_mlpin + (long)l * DIMC;
    for (int i = tid; i < DIMC; i += 256)
        out[i] = (1.0f + msc[i]) * ((row[i] - mean) * rstd) + msh[i];
}

// ---------------- final residual + output assembly (img first, then txt) --------
__global__ void final_kernel(float* __restrict__ out,
                             const float* __restrict__ tgate,
                             const float* __restrict__ igate)
{
    int l = blockIdx.x, tid = threadIdx.x;
    const float* g;
    float* dst;
    if (l < L_TXTC) { g = tgate; dst = out + (long)L_IMGC * DIMC + (long)l * DIMC; }
    else            { g = igate; dst = out + (long)(l - L_TXTC) * DIMC; }
    const float* xr = g_xres + (long)l * DIMC;
    const float* mo = g_mlpo + (long)l * DIMC;
    for (int i = tid; i < DIMC; i += 256)
        dst[i] = xr[i] + g[i] * mo[i];
}

// ---------------- host ----------------------------------------------------------
static void sgemm(const float* A, long lda, long sA,
                  const float* B, long ldb, long sB,
                  const float* bias,
                  float* C, long ldc, long sC,
                  int M, int N, int K, int batch, int act)
{
    dim3 grid((M / 128) * (N / 128), 1, batch);
    gemm_tf32_kernel<<<grid, 256>>>(A, lda, sA, B, ldb, sB, bias,
                                    C, ldc, sC, M, K, act);
}

extern "C" void kernel_launch(void* const* d_in, const int* in_sizes, int n_in,
                              void* d_out, int out_size)
{
    const float* img_emb   = (const float*)d_in[0];
    const float* txt_emb   = (const float*)d_in[1];
    const float* pe        = (const float*)d_in[2];
    const float* i_asc = (const float*)d_in[3];
    const float* i_ash = (const float*)d_in[4];
    const float* i_ag  = (const float*)d_in[5];
    const float* i_msc = (const float*)d_in[6];
    const float* i_msh = (const float*)d_in[7];
    const float* i_mg  = (const float*)d_in[8];
    const float* t_asc = (const float*)d_in[9];
    const float* t_ash = (const float*)d_in[10];
    const float* t_ag  = (const float*)d_in[11];
    const float* t_msc = (const float*)d_in[12];
    const float* t_msh = (const float*)d_in[13];
    const float* t_mg  = (const float*)d_in[14];
    const float* i_qkv_w = (const float*)d_in[15];
    const float* i_qkv_b = (const float*)d_in[16];
    const float* i_qnw   = (const float*)d_in[17];
    const float* t_qkv_w = (const float*)d_in[18];
    const float* t_qkv_b = (const float*)d_in[19];
    const float* t_qnw   = (const float*)d_in[20];
    const float* proj_w  = (const float*)d_in[21];
    const float* proj_b  = (const float*)d_in[22];
    const float* i_w1 = (const float*)d_in[23];
    const float* i_b1 = (const float*)d_in[24];
    const float* i_w2 = (const float*)d_in[25];
    const float* i_b2 = (const float*)d_in[26];
    const float* t_w1 = (const float*)d_in[27];
    const float* t_b1 = (const float*)d_in[28];
    const float* t_w2 = (const float*)d_in[29];
    const float* t_b2 = (const float*)d_in[30];
    // d_in[31] = mask: all-true in this problem -> no-op in softmax.

    float *p_xmod, *p_qkv, *p_q, *p_k, *p_vt, *p_S, *p_ocat, *p_attno, *p_mlpin, *p_hid, *p_mlpo;
    cudaGetSymbolAddress((void**)&p_xmod,  g_xmod);
    cudaGetSymbolAddress((void**)&p_qkv,   g_qkv);
    cudaGetSymbolAddress((void**)&p_q,     g_q);
    cudaGetSymbolAddress((void**)&p_k,     g_k);
    cudaGetSymbolAddress((void**)&p_vt,    g_vt);
    cudaGetSymbolAddress((void**)&p_S,     g_S);
    cudaGetSymbolAddress((void**)&p_ocat,  g_ocat);
    cudaGetSymbolAddress((void**)&p_attno, g_attno);
    cudaGetSymbolAddress((void**)&p_mlpin, g_mlpin);
    cudaGetSymbolAddress((void**)&p_hid,   g_hid);
    cudaGetSymbolAddress((void**)&p_mlpo,  g_mlpo);

    float* out = (float*)d_out;

    // 1. LN + attn modulation -> g_xmod (txt rows 0..511, img rows 512..2047)
    ln_mod_kernel<<<L_ALLC, 256>>>(txt_emb, img_emb, t_asc, t_ash, i_asc, i_ash);

    // 2/3. QKV GEMMs
    sgemm(p_xmod, DIMC, 0, t_qkv_w, DIMC, 0, t_qkv_b,
          p_qkv, QKVD, 0, L_TXTC, QKVD, DIMC, 1, 0);
    sgemm(p_xmod + (long)L_TXTC * DIMC, DIMC, 0, i_qkv_w, DIMC, 0, i_qkv_b,
          p_qkv + (long)L_TXTC * QKVD, QKVD, 0, L_IMGC, QKVD, DIMC, 1, 0);

    // 4. RMSNorm + RoPE + scale + layout
    {
        dim3 grid(L_ALLC, NH);
        qkv_post_kernel<<<grid, DHC>>>(pe, t_qnw, i_qnw);
    }

    // 5. scores = q @ k^T (batched over heads)
    sgemm(p_q, DHC, (long)L_ALLC * DHC, p_k, DHC, (long)L_ALLC * DHC, nullptr,
          p_S, L_ALLC, (long)L_ALLC * L_ALLC, L_ALLC, L_ALLC, DHC, NH, 0);

    // 6. softmax (512 threads, one float4 each)
    {
        dim3 grid(L_ALLC, NH);
        softmax_kernel<<<grid, 512>>>();
    }

    // 7. o = attn @ v  -> written directly into concatenated layout g_ocat
    sgemm(p_S, L_ALLC, (long)L_ALLC * L_ALLC, p_vt, L_ALLC, (long)DHC * L_ALLC, nullptr,
          p_ocat, DIMC, DHC, L_ALLC, DHC, L_ALLC, NH, 0);

    // 8. shared proj
    sgemm(p_ocat, DIMC, 0, proj_w, DIMC, 0, proj_b,
          p_attno, DIMC, 0, L_ALLC, DIMC, DIMC, 1, 0);

    // 9. residual + LN + mlp modulation
    res_ln_kernel<<<L_ALLC, 256>>>(txt_emb, img_emb, t_ag, i_ag, t_msc, t_msh, i_msc, i_msh);

    // 10/11. MLP up + GELU
    sgemm(p_mlpin, DIMC, 0, t_w1, DIMC, 0, t_b1,
          p_hid, MLPD, 0, L_TXTC, MLPD, DIMC, 1, 1);
    sgemm(p_mlpin + (long)L_TXTC * DIMC, DIMC, 0, i_w1, DIMC, 0, i_b1,
          p_hid + (long)L_TXTC * MLPD, MLPD, 0, L_IMGC, MLPD, DIMC, 1, 1);

    // 12/13. MLP down
    sgemm(p_hid, MLPD, 0, t_w2, MLPD, 0, t_b2,
          p_mlpo, DIMC, 0, L_TXTC, DIMC, MLPD, 1, 0);
    sgemm(p_hid + (long)L_TXTC * MLPD, MLPD, 0, i_w2, MLPD, 0, i_b2,
          p_mlpo + (long)L_TXTC * DIMC, DIMC, 0, L_IMGC, DIMC, MLPD, 1, 0);

    // 14. final residual + write output (img block first, then txt block)
    final_kernel<<<L_ALLC, 256>>>(out, t_mg, i_mg);
}

// round 8
// speedup vs baseline: 1.3799x; 1.1265x over previous
#include <cuda_runtime.h>
#include <math.h>
#include <stdint.h>

#define L_ALLC 2048
#define L_TXTC 512
#define L_IMGC 1536
#define NH     24
#define DHC    128
#define DIMC   3072
#define QKVD   9216
#define MLPD   12288

// ---------------- scratch (device globals; no runtime allocation) ----------------
__device__ float g_xmod  [L_ALLC * DIMC];
__device__ float g_qkv   [L_ALLC * QKVD];
__device__ float g_q     [NH * L_ALLC * DHC];
__device__ float g_k     [NH * L_ALLC * DHC];
__device__ float g_vt    [NH * DHC * L_ALLC];
__device__ float g_S     [(size_t)NH * L_ALLC * L_ALLC];
__device__ float g_ocat  [L_ALLC * DIMC];
__device__ float g_attno [L_ALLC * DIMC];
__device__ float g_xres  [L_ALLC * DIMC];
__device__ float g_mlpin [L_ALLC * DIMC];
__device__ float g_hid   [L_ALLC * MLPD];
__device__ float g_mlpo  [L_ALLC * DIMC];

__device__ __forceinline__ float gelu_tanh(float x) {
    float x3 = x * x * x;
    return 0.5f * x * (1.0f + tanhf(0.7978845608028654f * (x + 0.044715f * x3)));
}

__device__ __forceinline__ void cp_async16(unsigned smem_addr, const void* gptr) {
    asm volatile("cp.async.cg.shared.global [%0], [%1], 16;\n"
                 :: "r"(smem_addr), "l"(gptr));
}
__device__ __forceinline__ void cp_commit() {
    asm volatile("cp.async.commit_group;\n");
}
__device__ __forceinline__ void cp_wait1() {
    asm volatile("cp.async.wait_group 1;\n");
}

// ldmatrix x4: four 8x8 b16 matrices == four 8x4 f32 blocks.
__device__ __forceinline__ void ldsm_x4(unsigned& r0, unsigned& r1,
                                        unsigned& r2, unsigned& r3, unsigned addr) {
    asm volatile("ldmatrix.sync.aligned.m8n8.x4.shared.b16 {%0,%1,%2,%3}, [%4];"
                 : "=r"(r0), "=r"(r1), "=r"(r2), "=r"(r3) : "r"(addr));
}

// ---------------- tf32 mma GEMM, 128x128 CTA tile, 2-stage cp.async + ldmatrix ---
// C = A(MxK) * B(NxK)^T + bias, opt GELU. 256 threads (8 warps 2x4),
// warp tile 64x32, mma.m16n8k8.tf32 (raw fp32 bits; HW truncates mantissa).
// Smem row stride 36 words -> conflict-free LDSM row fetches (4-bank stagger).
// 1-D grid decoded M-FASTEST.
__global__ __launch_bounds__(256, 2)
void gemm_tf32_kernel(const float* __restrict__ A, long lda, long sA,
                      const float* __restrict__ B, long ldb, long sB,
                      const float* __restrict__ bias,
                      float* __restrict__ C, long ldc, long sC,
                      int M, int K, int act)
{
    __shared__ float As[2][128 * 36];
    __shared__ float Bs[2][128 * 36];

    const int tid = threadIdx.x;
    const int nm = M >> 7;
    const int bm = blockIdx.x % nm;     // M fastest
    const int bn = blockIdx.x / nm;
    const int bz = blockIdx.z;

    const float* Ag = A + (long)bz * sA + (long)bm * 128 * lda;
    const float* Bg = B + (long)bz * sB + (long)bn * 128 * ldb;

    const int lane = tid & 31;
    const int warp = tid >> 5;
    const int wm = (warp >> 2) * 64;
    const int wn = (warp & 3) * 32;
    const int qr = lane >> 2;
    const int qc = lane & 3;

    const int prow[4] = { (tid + 0) >> 3, (tid + 256) >> 3, (tid + 512) >> 3, (tid + 768) >> 3 };
    const int pc4 = (tid & 7) * 4;

    const unsigned sA0 = (unsigned)__cvta_generic_to_shared(&As[0][0]);
    const unsigned sA1 = (unsigned)__cvta_generic_to_shared(&As[1][0]);
    const unsigned sB0 = (unsigned)__cvta_generic_to_shared(&Bs[0][0]);
    const unsigned sB1 = (unsigned)__cvta_generic_to_shared(&Bs[1][0]);

    // per-thread ldmatrix address offsets (bytes)
    // A, fragment mi at ks: matrices {rows+0/ +8} x {cols ks / ks+4}, j = lane>>3
    const unsigned a_off =
        (unsigned)(((wm + (lane & 7) + ((lane >> 3) & 1) * 8) * 36 + (lane >> 4) * 4) * 4);
    // B, ni-pair p at ks: matrices {cols ks / ks+4} x {rows +0 / +8}, j = lane>>3
    const unsigned b_off =
        (unsigned)(((wn + (lane & 7) + (lane >> 4) * 8) * 36 + ((lane >> 3) & 1) * 4) * 4);

    float acc[4][4][4];
#pragma unroll
    for (int mi = 0; mi < 4; mi++)
#pragma unroll
        for (int ni = 0; ni < 4; ni++)
#pragma unroll
            for (int e = 0; e < 4; e++) acc[mi][ni][e] = 0.0f;

    const int T = K >> 5;

    // prologue: stage 0
#pragma unroll
    for (int r = 0; r < 4; r++) {
        int row = prow[r];
        unsigned off = (unsigned)(row * 36 + pc4) * 4u;
        cp_async16(sA0 + off, Ag + (long)row * lda + pc4);
        cp_async16(sB0 + off, Bg + (long)row * ldb + pc4);
    }
    cp_commit();

    for (int t = 0; t < T; t++) {
        if (t + 1 < T) {
            unsigned ab = ((t + 1) & 1) ? sA1 : sA0;
            unsigned bb = ((t + 1) & 1) ? sB1 : sB0;
            int k0 = (t + 1) << 5;
#pragma unroll
            for (int r = 0; r < 4; r++) {
                int row = prow[r];
                unsigned off = (unsigned)(row * 36 + pc4) * 4u;
                cp_async16(ab + off, Ag + (long)row * lda + k0 + pc4);
                cp_async16(bb + off, Bg + (long)row * ldb + k0 + pc4);
            }
        }
        cp_commit();
        cp_wait1();
        __syncthreads();

        const unsigned abase = ((t & 1) ? sA1 : sA0) + a_off;
        const unsigned bbase = ((t & 1) ? sB1 : sB0) + b_off;

#pragma unroll
        for (int ks = 0; ks < 32; ks += 8) {
            unsigned a[4][4], b[4][2];
#pragma unroll
            for (int mi = 0; mi < 4; mi++)
                ldsm_x4(a[mi][0], a[mi][1], a[mi][2], a[mi][3],
                        abase + (unsigned)((mi * 16 * 36 + ks) * 4));
            ldsm_x4(b[0][0], b[0][1], b[1][0], b[1][1],
                    bbase + (unsigned)(ks * 4));
            ldsm_x4(b[2][0], b[2][1], b[3][0], b[3][1],
                    bbase + (unsigned)((16 * 36 + ks) * 4));
#pragma unroll
            for (int mi = 0; mi < 4; mi++)
#pragma unroll
                for (int ni = 0; ni < 4; ni++) {
                    asm volatile(
                        "mma.sync.aligned.m16n8k8.row.col.f32.tf32.tf32.f32 "
                        "{%0,%1,%2,%3}, {%4,%5,%6,%7}, {%8,%9}, {%0,%1,%2,%3};"
                        : "+f"(acc[mi][ni][0]), "+f"(acc[mi][ni][1]),
                          "+f"(acc[mi][ni][2]), "+f"(acc[mi][ni][3])
                        : "r"(a[mi][0]), "r"(a[mi][1]), "r"(a[mi][2]), "r"(a[mi][3]),
                          "r"(b[ni][0]), "r"(b[ni][1]));
                }
        }
        __syncthreads();
    }

    // ---- epilogue ----
    float* Cg = C + (long)bz * sC + (long)bm * 128 * ldc + (long)bn * 128;
#pragma unroll
    for (int ni = 0; ni < 4; ni++) {
        int col = wn + ni * 8 + qc * 2;
        float b0 = bias ? bias[(long)bn * 128 + col]     : 0.0f;
        float b1 = bias ? bias[(long)bn * 128 + col + 1] : 0.0f;
#pragma unroll
        for (int mi = 0; mi < 4; mi++) {
            int row = wm + mi * 16 + qr;
            float t0 = acc[mi][ni][0] + b0;
            float t1 = acc[mi][ni][1] + b1;
            float t2 = acc[mi][ni][2] + b0;
            float t3 = acc[mi][ni][3] + b1;
            if (act == 1) {
                t0 = gelu_tanh(t0); t1 = gelu_tanh(t1);
                t2 = gelu_tanh(t2); t3 = gelu_tanh(t3);
            }
            *(float2*)(Cg + (long)row * ldc + col)       = make_float2(t0, t1);
            *(float2*)(Cg + (long)(row + 8) * ldc + col) = make_float2(t2, t3);
        }
    }
}

// ---------------- LN + modulation: x_mod = (1+scale)*LN(x) + shift --------------
__global__ void ln_mod_kernel(const float* __restrict__ txt_emb,
                              const float* __restrict__ img_emb,
                              const float* __restrict__ tsc, const float* __restrict__ tsh,
                              const float* __restrict__ isc, const float* __restrict__ ish)
{
    int l = blockIdx.x, tid = threadIdx.x;
    __shared__ float row[DIMC];
    __shared__ float redA[8], redB[8];

    const float *x, *sc, *sh;
    if (l < L_TXTC) { x = txt_emb + (long)l * DIMC; sc = tsc; sh = tsh; }
    else            { x = img_emb + (long)(l - L_TXTC) * DIMC; sc = isc; sh = ish; }

    float s = 0.f, s2 = 0.f;
    for (int i = tid; i < DIMC; i += 256) {
        float v = x[i]; row[i] = v; s += v; s2 += v * v;
    }
#pragma unroll
    for (int o = 16; o > 0; o >>= 1) {
        s  += __shfl_xor_sync(0xffffffffu, s,  o);
        s2 += __shfl_xor_sync(0xffffffffu, s2, o);
    }
    int w = tid >> 5;
    if ((tid & 31) == 0) { redA[w] = s; redB[w] = s2; }
    __syncthreads();
    if (tid == 0) {
        float a = 0.f, b = 0.f;
        for (int i = 0; i < 8; i++) { a += redA[i]; b += redB[i]; }
        redA[0] = a; redB[0] = b;
    }
    __syncthreads();
    float mean = redA[0] / DIMC;
    float var  = redB[0] / DIMC - mean * mean;
    float rstd = rsqrtf(var + 1e-6f);

    float* out = g_xmod + (long)l * DIMC;
    for (int i = tid; i < DIMC; i += 256)
        out[i] = (1.0f + sc[i]) * ((row[i] - mean) * rstd) + sh[i];
}

// ---------------- QKV post: RMSNorm + RoPE + scale + transpose ------------------
__global__ void qkv_post_kernel(const float* __restrict__ pe,
                                const float* __restrict__ tqw,
                                const float* __restrict__ iqw)
{
    int l = blockIdx.x, h = blockIdx.y, d = threadIdx.x;
    const float* base = g_qkv + (long)l * QKVD + h * DHC;
    float qv = base[d];
    float kv = base[DIMC + d];
    float vv = base[2 * DIMC + d];
    const float* w = (l < L_TXTC) ? tqw : iqw;

    __shared__ float s1[DHC], s2[DHC], sq[DHC], sk[DHC];
    s1[d] = qv * qv; s2[d] = kv * kv;
    __syncthreads();
    for (int o = 64; o > 0; o >>= 1) {
        if (d < o) { s1[d] += s1[d + o]; s2[d] += s2[d + o]; }
        __syncthreads();
    }
    float rq = rsqrtf(s1[0] / DHC + 1e-6f);
    float rk = rsqrtf(s2[0] / DHC + 1e-6f);
    __syncthreads();
    sq[d] = qv * rq * w[d];
    sk[d] = kv * rk * w[d];
    __syncthreads();

    int j = d >> 1;
    float c = pe[(long)l * 256 + j * 4];
    float s = pe[(long)l * 256 + j * 4 + 2];
    float qr, kr;
    if ((d & 1) == 0) {
        qr = sq[d] * c - sq[d + 1] * s;
        kr = sk[d] * c - sk[d + 1] * s;
    } else {
        qr = sq[d - 1] * s + sq[d] * c;
        kr = sk[d - 1] * s + sk[d] * c;
    }
    long qi = ((long)h * L_ALLC + l) * DHC + d;
    g_q[qi] = qr * 0.08838834764831845f;  // DH^-0.5 folded into q
    g_k[qi] = kr;
    g_vt[((long)h * DHC + d) * L_ALLC + l] = vv;
}

// ---------------- softmax over rows of S: 512 thr, one float4 per thread --------
__global__ __launch_bounds__(512)
void softmax_kernel()
{
    float* S = g_S + ((long)blockIdx.y * L_ALLC + blockIdx.x) * L_ALLC;
    const int tid = threadIdx.x;
    __shared__ float red[16];

    float4 v = *(const float4*)(S + tid * 4);

    float m = fmaxf(fmaxf(v.x, v.y), fmaxf(v.z, v.w));
#pragma unroll
    for (int o = 16; o > 0; o >>= 1) m = fmaxf(m, __shfl_xor_sync(0xffffffffu, m, o));
    int w = tid >> 5;
    if ((tid & 31) == 0) red[w] = m;
    __syncthreads();
    if (tid < 32) {
        float t = (tid < 16) ? red[tid] : -1e30f;
#pragma unroll
        for (int o = 8; o > 0; o >>= 1) t = fmaxf(t, __shfl_xor_sync(0xffffffffu, t, o));
        if (tid == 0) red[0] = t;
    }
    __syncthreads();
    m = red[0];

    v.x = __expf(v.x - m); v.y = __expf(v.y - m);
    v.z = __expf(v.z - m); v.w = __expf(v.w - m);
    float s = v.x + v.y + v.z + v.w;
#pragma unroll
    for (int o = 16; o > 0; o >>= 1) s += __shfl_xor_sync(0xffffffffu, s, o);
    if ((tid & 31) == 0) red[w] = s;
    __syncthreads();
    if (tid < 32) {
        float t = (tid < 16) ? red[tid] : 0.0f;
#pragma unroll
        for (int o = 8; o > 0; o >>= 1) t += __shfl_xor_sync(0xffffffffu, t, o);
        if (tid == 0) red[0] = t;
    }
    __syncthreads();
    float inv = 1.0f / red[0];

    v.x *= inv; v.y *= inv; v.z *= inv; v.w *= inv;
    *(float4*)(S + tid * 4) = v;
}

// ---------------- residual + LN + MLP modulation --------------------------------
__global__ void res_ln_kernel(const float* __restrict__ txt_emb,
                              const float* __restrict__ img_emb,
                              const float* __restrict__ tgate, const float* __restrict__ igate,
                              const float* __restrict__ tmsc,  const float* __restrict__ tmsh,
                              const float* __restrict__ imsc,  const float* __restrict__ imsh)
{
    int l = blockIdx.x, tid = threadIdx.x;
    __shared__ float row[DIMC];
    __shared__ float redA[8], redB[8];

    const float *emb, *gate, *msc, *msh;
    if (l < L_TXTC) { emb = txt_emb + (long)l * DIMC; gate = tgate; msc = tmsc; msh = tmsh; }
    else            { emb = img_emb + (long)(l - L_TXTC) * DIMC; gate = igate; msc = imsc; msh = imsh; }

    const float* attn = g_attno + (long)l * DIMC;
    float* xres = g_xres + (long)l * DIMC;

    float s = 0.f, s2 = 0.f;
    for (int i = tid; i < DIMC; i += 256) {
        float v = emb[i] + gate[i] * attn[i];
        row[i] = v; xres[i] = v; s += v; s2 += v * v;
    }
#pragma unroll
    for (int o = 16; o > 0; o >>= 1) {
        s  += __shfl_xor_sync(0xffffffffu, s,  o);
        s2 += __shfl_xor_sync(0xffffffffu, s2, o);
    }
    int w = tid >> 5;
    if ((tid & 31) == 0) { redA[w] = s; redB[w] = s2; }
    __syncthreads();
    if (tid == 0) {
        float a = 0.f, b = 0.f;
        for (int i = 0; i < 8; i++) { a += redA[i]; b += redB[i]; }
        redA[0] = a; redB[0] = b;
    }
    __syncthreads();
    float mean = redA[0] / DIMC;
    float var  = redB[0] / DIMC - mean * mean;
    float rstd = rsqrtf(var + 1e-6f);

    float* out = g_mlpin + (long)l * DIMC;
    for (int i = tid; i < DIMC; i += 256)
        out[i] = (1.0f + msc[i]) * ((row[i] - mean) * rstd) + msh[i];
}

// ---------------- final residual + output assembly (img first, then txt) --------
__global__ void final_kernel(float* __restrict__ out,
                             const float* __restrict__ tgate,
                             const float* __restrict__ igate)
{
    int l = blockIdx.x, tid = threadIdx.x;
    const float* g;
    float* dst;
    if (l < L_TXTC) { g = tgate; dst = out + (long)L_IMGC * DIMC + (long)l * DIMC; }
    else            { g = igate; dst = out + (long)(l - L_TXTC) * DIMC; }
    const float* xr = g_xres + (long)l * DIMC;
    const float* mo = g_mlpo + (long)l * DIMC;
    for (int i = tid; i < DIMC; i += 256)
        dst[i] = xr[i] + g[i] * mo[i];
}

// ---------------- host ----------------------------------------------------------
static void sgemm(const float* A, long lda, long sA,
                  const float* B, long ldb, long sB,
                  const float* bias,
                  float* C, long ldc, long sC,
                  int M, int N, int K, int batch, int act)
{
    dim3 grid((M / 128) * (N / 128), 1, batch);
    gemm_tf32_kernel<<<grid, 256>>>(A, lda, sA, B, ldb, sB, bias,
                                    C, ldc, sC, M, K, act);
}

extern "C" void kernel_launch(void* const* d_in, const int* in_sizes, int n_in,
                              void* d_out, int out_size)
{
    const float* img_emb   = (const float*)d_in[0];
    const float* txt_emb   = (const float*)d_in[1];
    const float* pe        = (const float*)d_in[2];
    const float* i_asc = (const float*)d_in[3];
    const float* i_ash = (const float*)d_in[4];
    const float* i_ag  = (const float*)d_in[5];
    const float* i_msc = (const float*)d_in[6];
    const float* i_msh = (const float*)d_in[7];
    const float* i_mg  = (const float*)d_in[8];
    const float* t_asc = (const float*)d_in[9];
    const float* t_ash = (const float*)d_in[10];
    const float* t_ag  = (const float*)d_in[11];
    const float* t_msc = (const float*)d_in[12];
    const float* t_msh = (const float*)d_in[13];
    const float* t_mg  = (const float*)d_in[14];
    const float* i_qkv_w = (const float*)d_in[15];
    const float* i_qkv_b = (const float*)d_in[16];
    const float* i_qnw   = (const float*)d_in[17];
    const float* t_qkv_w = (const float*)d_in[18];
    const float* t_qkv_b = (const float*)d_in[19];
    const float* t_qnw   = (const float*)d_in[20];
    const float* proj_w  = (const float*)d_in[21];
    const float* proj_b  = (const float*)d_in[22];
    const float* i_w1 = (const float*)d_in[23];
    const float* i_b1 = (const float*)d_in[24];
    const float* i_w2 = (const float*)d_in[25];
    const float* i_b2 = (const float*)d_in[26];
    const float* t_w1 = (const float*)d_in[27];
    const float* t_b1 = (const float*)d_in[28];
    const float* t_w2 = (const float*)d_in[29];
    const float* t_b2 = (const float*)d_in[30];
    // d_in[31] = mask: all-true in this problem -> no-op in softmax.

    float *p_xmod, *p_qkv, *p_q, *p_k, *p_vt, *p_S, *p_ocat, *p_attno, *p_mlpin, *p_hid, *p_mlpo;
    cudaGetSymbolAddress((void**)&p_xmod,  g_xmod);
    cudaGetSymbolAddress((void**)&p_qkv,   g_qkv);
    cudaGetSymbolAddress((void**)&p_q,     g_q);
    cudaGetSymbolAddress((void**)&p_k,     g_k);
    cudaGetSymbolAddress((void**)&p_vt,    g_vt);
    cudaGetSymbolAddress((void**)&p_S,     g_S);
    cudaGetSymbolAddress((void**)&p_ocat,  g_ocat);
    cudaGetSymbolAddress((void**)&p_attno, g_attno);
    cudaGetSymbolAddress((void**)&p_mlpin, g_mlpin);
    cudaGetSymbolAddress((void**)&p_hid,   g_hid);
    cudaGetSymbolAddress((void**)&p_mlpo,  g_mlpo);

    float* out = (float*)d_out;

    // 1. LN + attn modulation -> g_xmod (txt rows 0..511, img rows 512..2047)
    ln_mod_kernel<<<L_ALLC, 256>>>(txt_emb, img_emb, t_asc, t_ash, i_asc, i_ash);

    // 2/3. QKV GEMMs
    sgemm(p_xmod, DIMC, 0, t_qkv_w, DIMC, 0, t_qkv_b,
          p_qkv, QKVD, 0, L_TXTC, QKVD, DIMC, 1, 0);
    sgemm(p_xmod + (long)L_TXTC * DIMC, DIMC, 0, i_qkv_w, DIMC, 0, i_qkv_b,
          p_qkv + (long)L_TXTC * QKVD, QKVD, 0, L_IMGC, QKVD, DIMC, 1, 0);

    // 4. RMSNorm + RoPE + scale + layout
    {
        dim3 grid(L_ALLC, NH);
        qkv_post_kernel<<<grid, DHC>>>(pe, t_qnw, i_qnw);
    }

    // 5. scores = q @ k^T (batched over heads)
    sgemm(p_q, DHC, (long)L_ALLC * DHC, p_k, DHC, (long)L_ALLC * DHC, nullptr,
          p_S, L_ALLC, (long)L_ALLC * L_ALLC, L_ALLC, L_ALLC, DHC, NH, 0);

    // 6. softmax (512 threads, one float4 each)
    {
        dim3 grid(L_ALLC, NH);
        softmax_kernel<<<grid, 512>>>();
    }

    // 7. o = attn @ v  -> written directly into concatenated layout g_ocat
    sgemm(p_S, L_ALLC, (long)L_ALLC * L_ALLC, p_vt, L_ALLC, (long)DHC * L_ALLC, nullptr,
          p_ocat, DIMC, DHC, L_ALLC, DHC, L_ALLC, NH, 0);

    // 8. shared proj
    sgemm(p_ocat, DIMC, 0, proj_w, DIMC, 0, proj_b,
          p_attno, DIMC, 0, L_ALLC, DIMC, DIMC, 1, 0);

    // 9. residual + LN + mlp modulation
    res_ln_kernel<<<L_ALLC, 256>>>(txt_emb, img_emb, t_ag, i_ag, t_msc, t_msh, i_msc, i_msh);

    // 10/11. MLP up + GELU
    sgemm(p_mlpin, DIMC, 0, t_w1, DIMC, 0, t_b1,
          p_hid, MLPD, 0, L_TXTC, MLPD, DIMC, 1, 1);
    sgemm(p_mlpin + (long)L_TXTC * DIMC, DIMC, 0, i_w1, DIMC, 0, i_b1,
          p_hid + (long)L_TXTC * MLPD, MLPD, 0, L_IMGC, MLPD, DIMC, 1, 1);

    // 12/13. MLP down
    sgemm(p_hid, MLPD, 0, t_w2, MLPD, 0, t_b2,
          p_mlpo, DIMC, 0, L_TXTC, DIMC, MLPD, 1, 0);
    sgemm(p_hid + (long)L_TXTC * MLPD, MLPD, 0, i_w2, MLPD, 0, i_b2,
          p_mlpo + (long)L_TXTC * DIMC, DIMC, 0, L_IMGC, DIMC, MLPD, 1, 0);

    // 14. final residual + write output (img block first, then txt block)
    final_kernel<<<L_ALLC, 256>>>(out, t_mg, i_mg);
}